// round 12
// baseline (speedup 1.0000x reference)
#include <cuda_runtime.h>
#include <cstdint>

#define T_STEPS 50
#define BATCH   128
#define NIN     16384
#define NH      256
#define NO      11
#define M_TOT   (T_STEPS * BATCH)     // 6400

#define BM      64
#define BN      128
#define BK      32
#define CHUNKS  (NIN / BK)            // 512
#define KSPLIT  5
#define CPK     103                   // 103*4 + 100 = 512
#define FLUSH   8
#define EPS     2e-4f                 // flag margin (bound ~3e-5, 6x safety)

#define ROWB    48
#define XT_B    (64 * ROWB)
#define WT_B    (128 * ROWB)
#define SXI(lv)     ((uint32_t)(lv) * XT_B)
#define SWI(st, lv) (4 * XT_B + ((uint32_t)(st) * 4 + (lv)) * WT_B)
#define SMEM_DYN    (4 * XT_B + 8 * WT_B)   // 61440
#define FIX_SMEM    (NIN * 4)               // 65536 (W row)

// group scales: sx*sw*2^E, sx=2^-25, sw=2^-32 -> 2^(E-57)
#define S42 0x1p-15f
#define S35 0x1p-22f
#define S21 0x1p-36f

// ---------------------------------------------------------------------------
__device__ float g_part[(size_t)KSPLIT * M_TOT * NH];
__device__ float g_cur1[(size_t)M_TOT * NH];
__device__ char  g_wq[(size_t)4 * NH * NIN];
__device__ int   g_flags[1 + BATCH * NH];    // [0]=count, then chain ids

// ---------------------------------------------------------------------------
__device__ __forceinline__ uint32_t smem_u32(const void* p) {
    uint32_t a;
    asm("{ .reg .u64 t; cvta.to.shared.u64 t, %1; cvt.u32.u64 %0, t; }"
        : "=r"(a) : "l"(p));
    return a;
}

__device__ __forceinline__ uint32_t lds32(uint32_t addr) {
    uint32_t v;
    asm volatile("ld.shared.b32 %0, [%1];" : "=r"(v) : "r"(addr));
    return v;
}

__device__ __forceinline__ void imma(int* d, const uint32_t* a,
                                     uint32_t b0, uint32_t b1) {
    asm volatile(
        "mma.sync.aligned.m16n8k32.row.col.s32.s8.s8.s32 "
        "{%0,%1,%2,%3}, {%4,%5,%6,%7}, {%8,%9}, {%0,%1,%2,%3};"
        : "+r"(d[0]), "+r"(d[1]), "+r"(d[2]), "+r"(d[3])
        : "r"(a[0]), "r"(a[1]), "r"(a[2]), "r"(a[3]), "r"(b0), "r"(b1));
}

__device__ __forceinline__ void imma_z(int* d, const uint32_t* a,
                                       uint32_t b0, uint32_t b1) {
    asm volatile(
        "mma.sync.aligned.m16n8k32.row.col.s32.s8.s8.s32 "
        "{%0,%1,%2,%3}, {%4,%5,%6,%7}, {%8,%9}, {%10,%10,%10,%10};"
        : "=r"(d[0]), "=r"(d[1]), "=r"(d[2]), "=r"(d[3])
        : "r"(a[0]), "r"(a[1]), "r"(a[2]), "r"(a[3]), "r"(b0), "r"(b1),
          "r"(0));
}

__device__ __forceinline__ void cp16(uint32_t dst, const void* src) {
    asm volatile("cp.async.cg.shared.global [%0], [%1], 16;"
                 :: "r"(dst), "l"(src));
}
#define CP_COMMIT() asm volatile("cp.async.commit_group;" ::: "memory")
#define CP_WAIT1()  asm volatile("cp.async.wait_group 1;" ::: "memory")

__device__ __forceinline__ uint32_t pack4(int b0, int b1, int b2, int b3) {
    return (uint32_t)(b0 & 0xFF) | ((uint32_t)(b1 & 0xFF) << 8) |
           ((uint32_t)(b2 & 0xFF) << 16) | ((uint32_t)(b3 & 0xFF) << 24);
}

// ---------------------------------------------------------------------------
// Kernel 0: quantize W1 into 4 int8 planes (exact fixed-point decomposition)
// ---------------------------------------------------------------------------
__global__ __launch_bounds__(256) void convw1(const float* __restrict__ W1,
                                              char* __restrict__ wq) {
    const size_t gidx = (size_t)blockIdx.x * 256 + threadIdx.x;
    const size_t PL = (size_t)NH * NIN;
    float4 f = reinterpret_cast<const float4*>(W1)[gidx];
    int q1[4], q2[4], q3[4], q4[4];
    const float* fv = &f.x;
#pragma unroll
    for (int i = 0; i < 4; i++) {
        int wi = __float2int_rn(fv[i] * 4294967296.0f);   // exact pow2 scale
        int a = (wi + (1 << 20)) >> 21;  wi -= a << 21;
        int b = (wi + (1 << 13)) >> 14;  wi -= b << 14;
        int c = (wi + (1 << 6))  >> 7;   wi -= c << 7;
        q1[i] = a; q2[i] = b; q3[i] = c; q4[i] = wi;
    }
    reinterpret_cast<uint32_t*>(wq + 0 * PL)[gidx] = pack4(q1[0], q1[1], q1[2], q1[3]);
    reinterpret_cast<uint32_t*>(wq + 1 * PL)[gidx] = pack4(q2[0], q2[1], q2[2], q2[3]);
    reinterpret_cast<uint32_t*>(wq + 2 * PL)[gidx] = pack4(q3[0], q3[1], q3[2], q3[3]);
    reinterpret_cast<uint32_t*>(wq + 3 * PL)[gidx] = pack4(q4[0], q4[1], q4[2], q4[3]);
}

// ---------------------------------------------------------------------------
// Kernel 1: partial GEMM via exact int8 IMMA (round-9, consistency-proven)
// ---------------------------------------------------------------------------
__global__ __launch_bounds__(256) void gemm_i8(
    const float* __restrict__ X,
    const char* __restrict__ wq,
    float* __restrict__ part)
{
    extern __shared__ __align__(128) char smem[];
    const uint32_t sbase = smem_u32(smem);

    const int tid  = threadIdx.x;
    const int lane = tid & 31;
    const int wid  = tid >> 5;
    const int n0 = blockIdx.x * BN;
    const int m0 = blockIdx.y * BM;
    const int c0 = blockIdx.z * CPK;
    const int nch = min(CHUNKS - c0, CPK);
    const int warpM = wid & 1;
    const int warpN = wid >> 1;
    const int g  = lane >> 2;
    const int tq = lane & 3;
    const size_t PL = (size_t)NH * NIN;

    const int xr = tid >> 2;
    const int xc = (tid & 3) * 8;
    const float* xp = X + (size_t)(m0 + xr) * NIN + (size_t)c0 * BK + xc;
    const uint32_t xsts = (uint32_t)xr * ROWB + (uint32_t)xc;

    const int wlv = tid >> 6;
    const int wr  = (tid & 63) * 2;
    const char* wsrc = wq + (size_t)wlv * PL + (size_t)(n0 + wr) * NIN
                     + (size_t)c0 * BK;
    const uint32_t wsts = (uint32_t)wr * ROWB;

    const uint32_t a_base = (uint32_t)(warpM * 32 + g) * ROWB + (uint32_t)tq * 4;
    const uint32_t b_base = (uint32_t)(warpN * 32 + g) * ROWB + (uint32_t)tq * 4;

    int   G42[2][4][4], G35[2][4][4];
    float sumBig[2][4][4], sumC[2][4][4];
#pragma unroll
    for (int i = 0; i < 2; i++)
#pragma unroll
        for (int j = 0; j < 4; j++)
#pragma unroll
            for (int k = 0; k < 4; k++) {
                G42[i][j][k] = 0; G35[i][j][k] = 0;
                sumBig[i][j][k] = 0.0f; sumC[i][j][k] = 0.0f;
            }

#pragma unroll
    for (int j = 0; j < 2; j++)
#pragma unroll
        for (int i = 0; i < 2; i++)
            cp16(sbase + SWI(0, wlv) + wsts + j * ROWB + i * 16,
                 wsrc + (size_t)j * NIN + i * 16);
    CP_COMMIT();

    float4 fxa = *reinterpret_cast<const float4*>(xp);
    float4 fxb = *reinterpret_cast<const float4*>(xp + 4);

    for (int c = 0; c < nch; c++) {
        __syncthreads();

        {
            int q[4][8];
            const float* fa = &fxa.x;
            const float* fb = &fxb.x;
#pragma unroll
            for (int i = 0; i < 8; i++) {
                float v = (i < 4) ? fa[i] : fb[i - 4];
                int xi = __float2int_rn(v * 33554432.0f);   // x * 2^25, exact
                xi = max(-266338304, min(266338303, xi));
                int a = (xi + (1 << 20)) >> 21;  xi -= a << 21;
                int b = (xi + (1 << 13)) >> 14;  xi -= b << 14;
                int d = (xi + (1 << 6))  >> 7;   xi -= d << 7;
                q[0][i] = a; q[1][i] = b; q[2][i] = d; q[3][i] = xi;
            }
#pragma unroll
            for (int lv = 0; lv < 4; lv++) {
                uint2 p = make_uint2(pack4(q[lv][0], q[lv][1], q[lv][2], q[lv][3]),
                                     pack4(q[lv][4], q[lv][5], q[lv][6], q[lv][7]));
                *reinterpret_cast<uint2*>(smem + SXI(lv) + xsts) = p;
            }
        }

        if (c + 1 < nch) {
            const int st = (c + 1) & 1;
            const char* s = wsrc + (size_t)(c + 1) * BK;
#pragma unroll
            for (int j = 0; j < 2; j++)
#pragma unroll
                for (int i = 0; i < 2; i++)
                    cp16(sbase + SWI(st, wlv) + wsts + j * ROWB + i * 16,
                         s + (size_t)j * NIN + i * 16);
        }
        CP_COMMIT();

        if (c + 1 < nch) {
            const float* p = xp + (size_t)(c + 1) * BK;
            fxa = *reinterpret_cast<const float4*>(p);
            fxb = *reinterpret_cast<const float4*>(p + 4);
        }

        CP_WAIT1();
        __syncthreads();

        const int st = c & 1;

        uint32_t bf[4][4][2];
#pragma unroll
        for (int nt = 0; nt < 4; nt++) {
#pragma unroll
            for (int lv = 0; lv < 4; lv++) {
                const uint32_t bo = sbase + SWI(st, lv) + b_base
                                  + (uint32_t)nt * 8 * ROWB;
                bf[lv][nt][0] = lds32(bo);
                bf[lv][nt][1] = lds32(bo + 16);
            }
        }

#pragma unroll
        for (int mt = 0; mt < 2; mt++) {
            uint32_t a1[4], a2[4], a3[4], a4[4];
            {
                const uint32_t r0 = sbase + SXI(0) + a_base + (uint32_t)mt * 16 * ROWB;
                const uint32_t r1 = sbase + SXI(1) + a_base + (uint32_t)mt * 16 * ROWB;
                const uint32_t r2 = sbase + SXI(2) + a_base + (uint32_t)mt * 16 * ROWB;
                const uint32_t r3 = sbase + SXI(3) + a_base + (uint32_t)mt * 16 * ROWB;
                a1[0] = lds32(r0);      a1[1] = lds32(r0 + 8 * ROWB);
                a1[2] = lds32(r0 + 16); a1[3] = lds32(r0 + 8 * ROWB + 16);
                a2[0] = lds32(r1);      a2[1] = lds32(r1 + 8 * ROWB);
                a2[2] = lds32(r1 + 16); a2[3] = lds32(r1 + 8 * ROWB + 16);
                a3[0] = lds32(r2);      a3[1] = lds32(r2 + 8 * ROWB);
                a3[2] = lds32(r2 + 16); a3[3] = lds32(r2 + 8 * ROWB + 16);
                a4[0] = lds32(r3);      a4[1] = lds32(r3 + 8 * ROWB);
                a4[2] = lds32(r3 + 16); a4[3] = lds32(r3 + 8 * ROWB + 16);
            }
#pragma unroll
            for (int nt = 0; nt < 4; nt++) {
                imma(G42[mt][nt], a1, bf[0][nt][0], bf[0][nt][1]);
                imma(G35[mt][nt], a1, bf[1][nt][0], bf[1][nt][1]);
                imma(G35[mt][nt], a2, bf[0][nt][0], bf[0][nt][1]);
                int d28[4], d21[4];
                imma_z(d28, a1, bf[2][nt][0], bf[2][nt][1]);
                imma (d28, a2, bf[1][nt][0], bf[1][nt][1]);
                imma (d28, a3, bf[0][nt][0], bf[0][nt][1]);
                imma_z(d21, a1, bf[3][nt][0], bf[3][nt][1]);
                imma (d21, a2, bf[2][nt][0], bf[2][nt][1]);
                imma (d21, a3, bf[1][nt][0], bf[1][nt][1]);
                imma (d21, a4, bf[0][nt][0], bf[0][nt][1]);
#pragma unroll
                for (int k = 0; k < 4; k++) {
                    const int dc = d28[k] * 128 + d21[k];
                    sumC[mt][nt][k] = fmaf((float)dc, S21, sumC[mt][nt][k]);
                }
            }
        }

        if (((c & (FLUSH - 1)) == (FLUSH - 1)) || (c == nch - 1)) {
#pragma unroll
            for (int mt = 0; mt < 2; mt++)
#pragma unroll
                for (int nt = 0; nt < 4; nt++)
#pragma unroll
                    for (int k = 0; k < 4; k++) {
                        sumBig[mt][nt][k] = fmaf((float)G42[mt][nt][k], S42,
                                                 sumBig[mt][nt][k]);
                        sumBig[mt][nt][k] = fmaf((float)G35[mt][nt][k], S35,
                                                 sumBig[mt][nt][k]);
                        G42[mt][nt][k] = 0; G35[mt][nt][k] = 0;
                    }
        }
    }

    float* po = part + (size_t)blockIdx.z * M_TOT * NH;
#pragma unroll
    for (int nt = 0; nt < 4; nt++) {
        const int col = n0 + warpN * 32 + nt * 8 + tq * 2;
#pragma unroll
        for (int mt = 0; mt < 2; mt++) {
            const int row = m0 + warpM * 32 + mt * 16 + g;
            *reinterpret_cast<float2*>(po + (size_t)row * NH + col) =
                make_float2(sumBig[mt][nt][0] + sumC[mt][nt][0],
                            sumBig[mt][nt][1] + sumC[mt][nt][1]);
            *reinterpret_cast<float2*>(po + (size_t)(row + 8) * NH + col) =
                make_float2(sumBig[mt][nt][2] + sumC[mt][nt][2],
                            sumBig[mt][nt][3] + sumC[mt][nt][3]);
        }
    }
}

// ---------------------------------------------------------------------------
// Kernel 2: fold K-split partials + bias into cur1; flag risky chains.
// A chain (b,j) is risky if any pre-reset membrane comes within EPS of THR.
// ---------------------------------------------------------------------------
__global__ __launch_bounds__(256) void reduce_flag(
    const float* __restrict__ part,
    const float* __restrict__ b1,
    float* __restrict__ cur1,
    int* __restrict__ flags)
{
    const int b = blockIdx.x, j = threadIdx.x;
    const float bias = b1[j];
    const size_t P = (size_t)M_TOT * NH;
    const size_t base = (size_t)b * NH + j;
    const size_t ts = (size_t)BATCH * NH;

    float mem = 0.0f;
    bool risky = false;
#pragma unroll 5
    for (int t = 0; t < T_STEPS; t++) {
        const size_t idx = base + (size_t)t * ts;
        const float c = (((part[idx] + part[idx + P])
                        + (part[idx + 2 * P] + part[idx + 3 * P]))
                        + part[idx + 4 * P]) + bias;
        cur1[idx] = c;
        mem = 0.9f * mem + c;
        const float d = mem - 1.0f;
        risky |= (fabsf(d) < EPS);
        mem -= (d > 0.0f) ? 1.0f : 0.0f;
    }
    if (risky) {
        const int pos = atomicAdd(&flags[0], 1);
        flags[1 + pos] = b * NH + j;
    }
}

// ---------------------------------------------------------------------------
// Kernel 3: repair flagged chains with BITWISE round-1 arithmetic:
// cur1[t][b][j] = (sum_{k=0..16383 ascending} fmaf(X,W)) + b1[j].
// One CTA per flagged chain (looped), thread t handles timestep t;
// W row j staged in dynamic smem.
// ---------------------------------------------------------------------------
__global__ __launch_bounds__(128) void fix_chains(
    const float* __restrict__ X,
    const float* __restrict__ W1,
    const float* __restrict__ b1,
    float* __restrict__ cur1,
    const int* __restrict__ flags)
{
    extern __shared__ float ws[];      // W row: 16384 floats
    const int nf = flags[0];
    const int tid = threadIdx.x;

    for (int ci = blockIdx.x; ci < nf; ci += gridDim.x) {
        const int bj = flags[1 + ci];
        const int b = bj >> 8;
        const int j = bj & (NH - 1);

        // cooperative load of W row j
        const float4* wr4 = reinterpret_cast<const float4*>(W1 + (size_t)j * NIN);
        for (int i = tid; i < NIN / 4; i += blockDim.x)
            reinterpret_cast<float4*>(ws)[i] = wr4[i];
        __syncthreads();

        if (tid < T_STEPS) {
            const int t = tid;
            const float* xr = X + ((size_t)t * BATCH + b) * NIN;
            float acc = 0.0f;
            for (int k = 0; k < NIN; k += 8) {
                float4 xv0 = *reinterpret_cast<const float4*>(xr + k);
                float4 xv1 = *reinterpret_cast<const float4*>(xr + k + 4);
                acc = fmaf(xv0.x, ws[k + 0], acc);
                acc = fmaf(xv0.y, ws[k + 1], acc);
                acc = fmaf(xv0.z, ws[k + 2], acc);
                acc = fmaf(xv0.w, ws[k + 3], acc);
                acc = fmaf(xv1.x, ws[k + 4], acc);
                acc = fmaf(xv1.y, ws[k + 5], acc);
                acc = fmaf(xv1.z, ws[k + 6], acc);
                acc = fmaf(xv1.w, ws[k + 7], acc);
            }
            cur1[((size_t)t * BATCH + b) * NH + j] = acc + b1[j];
        }
        __syncthreads();
    }
}

// ---------------------------------------------------------------------------
// Kernel 4: VERBATIM round-1 fused scan (bitwise-passing downstream).
// ---------------------------------------------------------------------------
__global__ __launch_bounds__(256) void snn_scan(
    const float* __restrict__ cur1,
    const float* __restrict__ W2,
    const float* __restrict__ b2,
    float* __restrict__ out)
{
    const int b   = blockIdx.x;
    const int j   = threadIdx.x;
    const int wid = j >> 5;
    const int lid = j & 31;

    __shared__ float warp_sums[8][NO + 1];

    float w2c[NO];
#pragma unroll
    for (int o = 0; o < NO; o++) w2c[o] = W2[o * NH + j];

    float mem1 = 0.0f;
    float mem2 = 0.0f;
    const float bias2 = (j < NO) ? b2[j] : 0.0f;

    for (int t = 0; t < T_STEPS; t++) {
        const float c1 = cur1[((size_t)t * BATCH + b) * NH + j];
        mem1 = 0.9f * mem1 + c1;
        const float spk1 = (mem1 - 1.0f > 0.0f) ? 1.0f : 0.0f;
        mem1 -= spk1;

        float p[NO];
#pragma unroll
        for (int o = 0; o < NO; o++) p[o] = spk1 * w2c[o];

#pragma unroll
        for (int o = 0; o < NO; o++) {
#pragma unroll
            for (int off = 16; off > 0; off >>= 1)
                p[o] += __shfl_xor_sync(0xFFFFFFFFu, p[o], off);
        }
        if (lid == 0) {
#pragma unroll
            for (int o = 0; o < NO; o++) warp_sums[wid][o] = p[o];
        }
        __syncthreads();

        if (j < NO) {
            float c2 = bias2;
#pragma unroll
            for (int w = 0; w < 8; w++) c2 += warp_sums[w][j];
            mem2 = 0.9f * mem2 + c2;
            const float spk2 = (mem2 - 1.0f > 0.0f) ? 1.0f : 0.0f;
            mem2 -= spk2;
            out[((size_t)t * BATCH + b) * NO + j] = spk2;
        }
        __syncthreads();
    }
}

// ---------------------------------------------------------------------------
extern "C" void kernel_launch(void* const* d_in, const int* in_sizes, int n_in,
                              void* d_out, int out_size)
{
    const float* x  = (const float*)d_in[0];
    const float* W1 = (const float*)d_in[1];
    const float* b1 = (const float*)d_in[2];
    const float* W2 = (const float*)d_in[3];
    const float* b2 = (const float*)d_in[4];
    float* out = (float*)d_out;

    float *partp, *cur1;
    char* wqp;
    int* flagsp;
    cudaGetSymbolAddress((void**)&partp, g_part);
    cudaGetSymbolAddress((void**)&cur1, g_cur1);
    cudaGetSymbolAddress((void**)&wqp, g_wq);
    cudaGetSymbolAddress((void**)&flagsp, g_flags);

    cudaFuncSetAttribute(gemm_i8,
                         cudaFuncAttributeMaxDynamicSharedMemorySize, SMEM_DYN);
    cudaFuncSetAttribute(fix_chains,
                         cudaFuncAttributeMaxDynamicSharedMemorySize, FIX_SMEM);

    cudaMemsetAsync(flagsp, 0, sizeof(int));
    convw1<<<(NH * NIN / 4) / 256, 256>>>(W1, wqp);
    gemm_i8<<<dim3(2, 100, KSPLIT), 256, SMEM_DYN>>>(x, wqp, partp);
    reduce_flag<<<BATCH, NH>>>(partp, b1, cur1, flagsp);
    fix_chains<<<148, 128, FIX_SMEM>>>(x, W1, b1, cur1, flagsp);
    snn_scan<<<BATCH, NH>>>(cur1, W2, b2, out);
}

// round 13
// speedup vs baseline: 1.1886x; 1.1886x over previous
#include <cuda_runtime.h>
#include <cstdint>

#define T_STEPS 50
#define BATCH   128
#define NIN     16384
#define NH      256
#define NO      11
#define M_TOT   (T_STEPS * BATCH)     // 6400

#define CHUNKS  (NIN / 32)            // 512
#define EPS     3e-4f

#define PLX     ((size_t)M_TOT * NIN)
#define PLW     ((size_t)NH * NIN)

#define ROWB    48                    // 32 s8 + 16B pad per row
#define TILEB   (64 * ROWB)           // 3072 per plane
#define STAGEB  (6 * TILEB)           // 18432 (3 X planes + 3 W planes)
#define GSMEM   (2 * STAGEB)          // 36864 double-buffered

// group scales: sx*sw*2^E, sx=2^-18, sw=2^-25 -> 2^(E-43)
#define S28 0x1p-15f
#define S21 0x1p-22f
#define S14 0x1p-29f

// ---------------------------------------------------------------------------
// Device scratch
// ---------------------------------------------------------------------------
__device__ char  g_xq[3 * PLX];       // 3 int8 planes of X (315 MB)
__device__ char  g_wq[3 * PLW];       // 3 int8 planes of W1 (12 MB)
__device__ float g_cur1[(size_t)M_TOT * NH];
__device__ int   g_flags[1 + BATCH * NH];

// ---------------------------------------------------------------------------
// helpers
// ---------------------------------------------------------------------------
__device__ __forceinline__ uint32_t smem_u32(const void* p) {
    uint32_t a;
    asm("{ .reg .u64 t; cvta.to.shared.u64 t, %1; cvt.u32.u64 %0, t; }"
        : "=r"(a) : "l"(p));
    return a;
}

__device__ __forceinline__ uint32_t lds32(uint32_t addr) {
    uint32_t v;
    asm volatile("ld.shared.b32 %0, [%1];" : "=r"(v) : "r"(addr));
    return v;
}

// s8 mma, s32 accumulate chained in D/C (EXACT integer arithmetic)
__device__ __forceinline__ void imma(int* d, const uint32_t* a,
                                     uint32_t b0, uint32_t b1) {
    asm volatile(
        "mma.sync.aligned.m16n8k32.row.col.s32.s8.s8.s32 "
        "{%0,%1,%2,%3}, {%4,%5,%6,%7}, {%8,%9}, {%0,%1,%2,%3};"
        : "+r"(d[0]), "+r"(d[1]), "+r"(d[2]), "+r"(d[3])
        : "r"(a[0]), "r"(a[1]), "r"(a[2]), "r"(a[3]), "r"(b0), "r"(b1));
}

__device__ __forceinline__ void cp16(uint32_t dst, const void* src) {
    asm volatile("cp.async.cg.shared.global [%0], [%1], 16;"
                 :: "r"(dst), "l"(src));
}
#define CP_COMMIT() asm volatile("cp.async.commit_group;" ::: "memory")
#define CP_WAIT1()  asm volatile("cp.async.wait_group 1;" ::: "memory")

__device__ __forceinline__ uint32_t pack4(int b0, int b1, int b2, int b3) {
    return (uint32_t)(b0 & 0xFF) | ((uint32_t)(b1 & 0xFF) << 8) |
           ((uint32_t)(b2 & 0xFF) << 16) | ((uint32_t)(b3 & 0xFF) << 24);
}

// exact 3-level s8 decomposition of round(v*scale), clamp keeps x1 in s8
__device__ __forceinline__ void q3(float v, float scale,
                                   int& p1, int& p2, int& p3) {
    int xi = __float2int_rn(v * scale);
    xi = max(-2088960, min(2088959, xi));
    p1 = (xi + 8192) >> 14;  xi -= p1 << 14;
    p2 = (xi + 64) >> 7;     p3 = xi - (p2 << 7);
}

// ---------------------------------------------------------------------------
// Kernel 0a: quantize W1 -> 3 int8 planes
// ---------------------------------------------------------------------------
__global__ __launch_bounds__(256) void convw(const float* __restrict__ W1,
                                             char* __restrict__ wq) {
    const size_t gi = (size_t)blockIdx.x * 256 + threadIdx.x;
    float4 f = reinterpret_cast<const float4*>(W1)[gi];
    int a[4], b[4], c[4];
    q3(f.x, 33554432.0f, a[0], b[0], c[0]);   // 2^25
    q3(f.y, 33554432.0f, a[1], b[1], c[1]);
    q3(f.z, 33554432.0f, a[2], b[2], c[2]);
    q3(f.w, 33554432.0f, a[3], b[3], c[3]);
    reinterpret_cast<uint32_t*>(wq)[gi]           = pack4(a[0], a[1], a[2], a[3]);
    reinterpret_cast<uint32_t*>(wq + PLW)[gi]     = pack4(b[0], b[1], b[2], b[3]);
    reinterpret_cast<uint32_t*>(wq + 2 * PLW)[gi] = pack4(c[0], c[1], c[2], c[3]);
}

// ---------------------------------------------------------------------------
// Kernel 0b: quantize X -> 3 int8 planes (bandwidth bound, once)
// ---------------------------------------------------------------------------
__global__ __launch_bounds__(256) void convx(const float* __restrict__ X,
                                             char* __restrict__ xq) {
    const size_t gi = (size_t)blockIdx.x * 256 + threadIdx.x;
    float4 f = reinterpret_cast<const float4*>(X)[gi];
    int a[4], b[4], c[4];
    q3(f.x, 262144.0f, a[0], b[0], c[0]);     // 2^18
    q3(f.y, 262144.0f, a[1], b[1], c[1]);
    q3(f.z, 262144.0f, a[2], b[2], c[2]);
    q3(f.w, 262144.0f, a[3], b[3], c[3]);
    reinterpret_cast<uint32_t*>(xq)[gi]           = pack4(a[0], a[1], a[2], a[3]);
    reinterpret_cast<uint32_t*>(xq + PLX)[gi]     = pack4(b[0], b[1], b[2], b[3]);
    reinterpret_cast<uint32_t*>(xq + 2 * PLX)[gi] = pack4(c[0], c[1], c[2], c[3]);
}

// ---------------------------------------------------------------------------
// Kernel 1: cur1 = Xq @ Wq^T (6 exact int8 groups) + b1
// CTA 64x64, 256 threads (8 warps: 2M x 4N, warp tile 32x16).
// All groups resident s32, drained every 16 chunks (|G| < 2^24 worst-case
// -> exact I2F). No conversions in the hot loop. grid (4, 100).
// ---------------------------------------------------------------------------
__global__ __launch_bounds__(256, 2) void gemm_i8(
    const char* __restrict__ xq,
    const char* __restrict__ wq,
    const float* __restrict__ b1,
    float* __restrict__ cur1)
{
    extern __shared__ __align__(128) char smem[];
    const uint32_t sbase = smem_u32(smem);

    const int tid  = threadIdx.x;
    const int wid  = tid >> 5;
    const int lane = tid & 31;
    const int n0 = blockIdx.x * 64;
    const int m0 = blockIdx.y * 64;
    const int warpM = wid & 1;        // 2 M-groups of 32 rows
    const int warpN = wid >> 1;       // 4 N-groups of 16 cols
    const int g  = lane >> 2;
    const int tq = lane & 3;

    // ---- cp.async task precompute: 3 tasks/thread, 768 tasks/chunk ----
    const char* srcb[3];
    uint32_t dstb[3];
#pragma unroll
    for (int q = 0; q < 3; q++) {
        const int task = tid + q * 256;
        const int p = task >> 7;           // 0..5 (0-2 X planes, 3-5 W planes)
        const int r = (task >> 1) & 63;
        const int s = task & 1;
        srcb[q] = (p < 3)
            ? xq + (size_t)p * PLX + (size_t)(m0 + r) * NIN + s * 16
            : wq + (size_t)(p - 3) * PLW + (size_t)(n0 + r) * NIN + s * 16;
        dstb[q] = (uint32_t)(p * TILEB + r * ROWB + s * 16);
    }

    // ---- fragment base addresses (proven R9 maps) ----
    const uint32_t a_base = (uint32_t)(warpM * 32 + g) * ROWB + (uint32_t)tq * 4;
    const uint32_t b_base = (uint32_t)(warpN * 16 + g) * ROWB + (uint32_t)tq * 4;

    int   G28[2][2][4], G21[2][2][4], G14[2][2][4];
    float sum[2][2][4];
#pragma unroll
    for (int i = 0; i < 2; i++)
#pragma unroll
        for (int j = 0; j < 2; j++)
#pragma unroll
            for (int k = 0; k < 4; k++) {
                G28[i][j][k] = 0; G21[i][j][k] = 0; G14[i][j][k] = 0;
                sum[i][j][k] = 0.0f;
            }

    // ---- prologue: chunk 0 -> stage 0 ----
#pragma unroll
    for (int q = 0; q < 3; q++)
        cp16(sbase + dstb[q], srcb[q]);
    CP_COMMIT();

    // ---- mainloop ----
    for (int c = 0; c < CHUNKS; c++) {
        if (c + 1 < CHUNKS) {
            const uint32_t stoff = (uint32_t)((c + 1) & 1) * STAGEB;
#pragma unroll
            for (int q = 0; q < 3; q++)
                cp16(sbase + stoff + dstb[q], srcb[q] + (size_t)(c + 1) * 32);
        }
        CP_COMMIT();
        CP_WAIT1();
        __syncthreads();

        const uint32_t sb = sbase + (uint32_t)(c & 1) * STAGEB;

        uint32_t bf[3][2][2];
#pragma unroll
        for (int nt = 0; nt < 2; nt++) {
            const uint32_t bo = sb + 3 * TILEB + b_base
                              + (uint32_t)nt * 8 * ROWB;
#pragma unroll
            for (int p = 0; p < 3; p++) {
                bf[p][nt][0] = lds32(bo + p * TILEB);
                bf[p][nt][1] = lds32(bo + p * TILEB + 16);
            }
        }

#pragma unroll
        for (int mt = 0; mt < 2; mt++) {
            const uint32_t ao = sb + a_base + (uint32_t)mt * 16 * ROWB;
            uint32_t a1[4], a2[4], a3[4];
            a1[0] = lds32(ao);                    a1[1] = lds32(ao + 8 * ROWB);
            a1[2] = lds32(ao + 16);               a1[3] = lds32(ao + 8 * ROWB + 16);
            a2[0] = lds32(ao + TILEB);            a2[1] = lds32(ao + TILEB + 8 * ROWB);
            a2[2] = lds32(ao + TILEB + 16);       a2[3] = lds32(ao + TILEB + 8 * ROWB + 16);
            a3[0] = lds32(ao + 2 * TILEB);        a3[1] = lds32(ao + 2 * TILEB + 8 * ROWB);
            a3[2] = lds32(ao + 2 * TILEB + 16);   a3[3] = lds32(ao + 2 * TILEB + 8 * ROWB + 16);
#pragma unroll
            for (int nt = 0; nt < 2; nt++) {
                imma(G28[mt][nt], a1, bf[0][nt][0], bf[0][nt][1]);  // x1w1
                imma(G21[mt][nt], a1, bf[1][nt][0], bf[1][nt][1]);  // x1w2
                imma(G21[mt][nt], a2, bf[0][nt][0], bf[0][nt][1]);  // x2w1
                imma(G14[mt][nt], a1, bf[2][nt][0], bf[2][nt][1]);  // x1w3
                imma(G14[mt][nt], a2, bf[1][nt][0], bf[1][nt][1]);  // x2w2
                imma(G14[mt][nt], a3, bf[0][nt][0], bf[0][nt][1]);  // x3w1
            }
        }
        __syncthreads();

        // drain every 16 chunks (worst-case |G| < 2^24 -> exact I2F)
        if ((c & 15) == 15) {
#pragma unroll
            for (int mt = 0; mt < 2; mt++)
#pragma unroll
                for (int nt = 0; nt < 2; nt++)
#pragma unroll
                    for (int k = 0; k < 4; k++) {
                        float s = sum[mt][nt][k];
                        s = fmaf((float)G28[mt][nt][k], S28, s);
                        s = fmaf((float)G21[mt][nt][k], S21, s);
                        s = fmaf((float)G14[mt][nt][k], S14, s);
                        sum[mt][nt][k] = s;
                        G28[mt][nt][k] = 0; G21[mt][nt][k] = 0; G14[mt][nt][k] = 0;
                    }
        }
    }

    // ---- epilogue: + bias, store cur1 ----
#pragma unroll
    for (int nt = 0; nt < 2; nt++) {
        const int col = n0 + warpN * 16 + nt * 8 + tq * 2;
        const float bv0 = b1[col];
        const float bv1 = b1[col + 1];
#pragma unroll
        for (int mt = 0; mt < 2; mt++) {
            const int row = m0 + warpM * 32 + mt * 16 + g;
            *reinterpret_cast<float2*>(cur1 + (size_t)row * NH + col) =
                make_float2(sum[mt][nt][0] + bv0, sum[mt][nt][1] + bv1);
            *reinterpret_cast<float2*>(cur1 + (size_t)(row + 8) * NH + col) =
                make_float2(sum[mt][nt][2] + bv0, sum[mt][nt][3] + bv1);
        }
    }
}

// ---------------------------------------------------------------------------
// Kernel 2: flag chains whose membrane ever comes within EPS of threshold
// ---------------------------------------------------------------------------
__global__ __launch_bounds__(256) void flag_scan(const float* __restrict__ cur1,
                                                 int* __restrict__ flags) {
    const int b = blockIdx.x, j = threadIdx.x;
    const size_t base = (size_t)b * NH + j;
    const size_t ts = (size_t)BATCH * NH;
    float mem = 0.0f;
    bool risky = false;
#pragma unroll 5
    for (int t = 0; t < T_STEPS; t++) {
        const float c = cur1[base + (size_t)t * ts];
        mem = 0.9f * mem + c;
        const float d = mem - 1.0f;
        risky |= (fabsf(d) < EPS);
        mem -= (d > 0.0f) ? 1.0f : 0.0f;
    }
    if (risky) {
        const int pos = atomicAdd(&flags[0], 1);
        flags[1 + pos] = (b << 8) | j;
    }
}

// ---------------------------------------------------------------------------
// Kernel 3: repair flagged chains, BITWISE round-1 arithmetic.
// One thread per (chain, t) output; grid-stride.
// ---------------------------------------------------------------------------
__global__ __launch_bounds__(256) void fix2(
    const float* __restrict__ X,
    const float* __restrict__ W1,
    const float* __restrict__ b1,
    float* __restrict__ cur1,
    const int* __restrict__ flags)
{
    const int total = flags[0] * T_STEPS;
    for (int idx = blockIdx.x * blockDim.x + threadIdx.x; idx < total;
         idx += gridDim.x * blockDim.x) {
        const int ci = idx / T_STEPS;
        const int t  = idx - ci * T_STEPS;
        const int bj = flags[1 + ci];
        const int b = bj >> 8, j = bj & (NH - 1);
        const float* xr = X + ((size_t)t * BATCH + b) * NIN;
        const float* wr = W1 + (size_t)j * NIN;
        float acc = 0.0f;
        for (int k = 0; k < NIN; k += 8) {
            float4 x0 = *reinterpret_cast<const float4*>(xr + k);
            float4 x1 = *reinterpret_cast<const float4*>(xr + k + 4);
            float4 w0 = *reinterpret_cast<const float4*>(wr + k);
            float4 w1 = *reinterpret_cast<const float4*>(wr + k + 4);
            acc = fmaf(x0.x, w0.x, acc);
            acc = fmaf(x0.y, w0.y, acc);
            acc = fmaf(x0.z, w0.z, acc);
            acc = fmaf(x0.w, w0.w, acc);
            acc = fmaf(x1.x, w1.x, acc);
            acc = fmaf(x1.y, w1.y, acc);
            acc = fmaf(x1.z, w1.z, acc);
            acc = fmaf(x1.w, w1.w, acc);
        }
        cur1[((size_t)t * BATCH + b) * NH + j] = acc + b1[j];
    }
}

// ---------------------------------------------------------------------------
// Kernel 4: VERBATIM round-1 fused scan (bitwise-passing downstream).
// ---------------------------------------------------------------------------
__global__ __launch_bounds__(256) void snn_scan(
    const float* __restrict__ cur1,
    const float* __restrict__ W2,
    const float* __restrict__ b2,
    float* __restrict__ out)
{
    const int b   = blockIdx.x;
    const int j   = threadIdx.x;
    const int wid = j >> 5;
    const int lid = j & 31;

    __shared__ float warp_sums[8][NO + 1];

    float w2c[NO];
#pragma unroll
    for (int o = 0; o < NO; o++) w2c[o] = W2[o * NH + j];

    float mem1 = 0.0f;
    float mem2 = 0.0f;
    const float bias2 = (j < NO) ? b2[j] : 0.0f;

    for (int t = 0; t < T_STEPS; t++) {
        const float c1 = cur1[((size_t)t * BATCH + b) * NH + j];
        mem1 = 0.9f * mem1 + c1;
        const float spk1 = (mem1 - 1.0f > 0.0f) ? 1.0f : 0.0f;
        mem1 -= spk1;

        float p[NO];
#pragma unroll
        for (int o = 0; o < NO; o++) p[o] = spk1 * w2c[o];

#pragma unroll
        for (int o = 0; o < NO; o++) {
#pragma unroll
            for (int off = 16; off > 0; off >>= 1)
                p[o] += __shfl_xor_sync(0xFFFFFFFFu, p[o], off);
        }
        if (lid == 0) {
#pragma unroll
            for (int o = 0; o < NO; o++) warp_sums[wid][o] = p[o];
        }
        __syncthreads();

        if (j < NO) {
            float c2 = bias2;
#pragma unroll
            for (int w = 0; w < 8; w++) c2 += warp_sums[w][j];
            mem2 = 0.9f * mem2 + c2;
            const float spk2 = (mem2 - 1.0f > 0.0f) ? 1.0f : 0.0f;
            mem2 -= spk2;
            out[((size_t)t * BATCH + b) * NO + j] = spk2;
        }
        __syncthreads();
    }
}

// ---------------------------------------------------------------------------
extern "C" void kernel_launch(void* const* d_in, const int* in_sizes, int n_in,
                              void* d_out, int out_size)
{
    const float* x  = (const float*)d_in[0];
    const float* W1 = (const float*)d_in[1];
    const float* b1 = (const float*)d_in[2];
    const float* W2 = (const float*)d_in[3];
    const float* b2 = (const float*)d_in[4];
    float* out = (float*)d_out;

    float* cur1;
    char *xqp, *wqp;
    int* flagsp;
    cudaGetSymbolAddress((void**)&cur1, g_cur1);
    cudaGetSymbolAddress((void**)&xqp, g_xq);
    cudaGetSymbolAddress((void**)&wqp, g_wq);
    cudaGetSymbolAddress((void**)&flagsp, g_flags);

    cudaFuncSetAttribute(gemm_i8,
                         cudaFuncAttributeMaxDynamicSharedMemorySize, GSMEM);

    cudaMemsetAsync(flagsp, 0, sizeof(int));
    convw<<<(int)(PLW / 4 / 256), 256>>>(W1, wqp);
    convx<<<(int)(PLX / 4 / 256), 256>>>(x, xqp);
    gemm_i8<<<dim3(4, 100), 256, GSMEM>>>(xqp, wqp, b1, cur1);
    flag_scan<<<BATCH, NH>>>(cur1, flagsp);
    fix2<<<256, 256>>>(x, W1, b1, cur1, flagsp);
    snn_scan<<<BATCH, NH>>>(cur1, W2, b2, out);
}

// round 14
// speedup vs baseline: 3.2444x; 2.7295x over previous
#include <cuda_runtime.h>

#define T_STEPS 50
#define BATCH   128
#define NIN     16384
#define NH      256
#define NO      11
#define M_TOT   (T_STEPS * BATCH)   // 6400

// Scratch
__device__ float g_cur1[M_TOT * NH];
__device__ float g_spk1[M_TOT * NH];
__device__ float g_cur2[M_TOT * NO];

// ---------------------------------------------------------------------------
// GEMM: out[m][n] = sum_k X[m][k] * W1[n][k] + b1[n]  -- VERBATIM round-1
// kernel (bitwise-matches the reference's passing arithmetic; measured at
// ~97% of the fp32 FFMA issue roofline).
// ---------------------------------------------------------------------------
#define BM  64
#define BN  64
#define BKK 16
#define PAD 4

__global__ __launch_bounds__(128) void gemm_x_w1(
    const float* __restrict__ X,
    const float* __restrict__ W1,
    const float* __restrict__ b1,
    float* __restrict__ out)
{
    __shared__ float As[BKK][BM + PAD];  // [k][m]
    __shared__ float Bs[BKK][BN + PAD];  // [k][n]

    const int tid = threadIdx.x;           // 0..127
    const int tx  = tid & 15;              // 0..15 -> 4 cols each
    const int ty  = tid >> 4;              // 0..7  -> 8 rows each
    const int m0  = blockIdx.y * BM;
    const int n0  = blockIdx.x * BN;

    const int lr = tid >> 1;               // 0..63
    const int lc = (tid & 1) * 8;          // 0 or 8

    const float* __restrict__ aptr = X  + (size_t)(m0 + lr) * NIN + lc;
    const float* __restrict__ bptr = W1 + (size_t)(n0 + lr) * NIN + lc;

    float acc[8][4];
#pragma unroll
    for (int i = 0; i < 8; i++)
#pragma unroll
        for (int j = 0; j < 4; j++) acc[i][j] = 0.0f;

    float4 a0 = *reinterpret_cast<const float4*>(aptr + 0);
    float4 a1 = *reinterpret_cast<const float4*>(aptr + 4);
    float4 b0 = *reinterpret_cast<const float4*>(bptr + 0);
    float4 b1v = *reinterpret_cast<const float4*>(bptr + 4);

    for (int k0 = 0; k0 < NIN; k0 += BKK) {
        As[lc + 0][lr] = a0.x; As[lc + 1][lr] = a0.y;
        As[lc + 2][lr] = a0.z; As[lc + 3][lr] = a0.w;
        As[lc + 4][lr] = a1.x; As[lc + 5][lr] = a1.y;
        As[lc + 6][lr] = a1.z; As[lc + 7][lr] = a1.w;
        Bs[lc + 0][lr] = b0.x; Bs[lc + 1][lr] = b0.y;
        Bs[lc + 2][lr] = b0.z; Bs[lc + 3][lr] = b0.w;
        Bs[lc + 4][lr] = b1v.x; Bs[lc + 5][lr] = b1v.y;
        Bs[lc + 6][lr] = b1v.z; Bs[lc + 7][lr] = b1v.w;
        __syncthreads();

        if (k0 + BKK < NIN) {
            const float* ap = aptr + k0 + BKK;
            const float* bp = bptr + k0 + BKK;
            a0  = *reinterpret_cast<const float4*>(ap + 0);
            a1  = *reinterpret_cast<const float4*>(ap + 4);
            b0  = *reinterpret_cast<const float4*>(bp + 0);
            b1v = *reinterpret_cast<const float4*>(bp + 4);
        }

#pragma unroll
        for (int kk = 0; kk < BKK; kk++) {
            float a[8], b[4];
            float4 av0 = *reinterpret_cast<const float4*>(&As[kk][ty * 8 + 0]);
            float4 av1 = *reinterpret_cast<const float4*>(&As[kk][ty * 8 + 4]);
            float4 bv  = *reinterpret_cast<const float4*>(&Bs[kk][tx * 4]);
            a[0] = av0.x; a[1] = av0.y; a[2] = av0.z; a[3] = av0.w;
            a[4] = av1.x; a[5] = av1.y; a[6] = av1.z; a[7] = av1.w;
            b[0] = bv.x;  b[1] = bv.y;  b[2] = bv.z;  b[3] = bv.w;
#pragma unroll
            for (int i = 0; i < 8; i++)
#pragma unroll
                for (int j = 0; j < 4; j++)
                    acc[i][j] = fmaf(a[i], b[j], acc[i][j]);
        }
        __syncthreads();
    }

    float4 bias = *reinterpret_cast<const float4*>(b1 + n0 + tx * 4);
#pragma unroll
    for (int i = 0; i < 8; i++) {
        const int m = m0 + ty * 8 + i;
        float4 v;
        v.x = acc[i][0] + bias.x;
        v.y = acc[i][1] + bias.y;
        v.z = acc[i][2] + bias.z;
        v.w = acc[i][3] + bias.w;
        *reinterpret_cast<float4*>(out + (size_t)m * NH + n0 + tx * 4) = v;
    }
}

// ---------------------------------------------------------------------------
// scan1: 32768 independent layer-1 membrane chains, parallel over (b, j).
// Identical source expressions to round-1's snn_scan -> identical codegen
// -> bitwise-identical spk1.
// ---------------------------------------------------------------------------
__global__ __launch_bounds__(256) void scan1(const float* __restrict__ cur1,
                                             float* __restrict__ spk1) {
    const int b = blockIdx.x, j = threadIdx.x;
    float mem1 = 0.0f;
#pragma unroll 5
    for (int t = 0; t < T_STEPS; t++) {
        const float c1 = cur1[((size_t)t * BATCH + b) * NH + j];
        mem1 = 0.9f * mem1 + c1;
        const float spk = (mem1 - 1.0f > 0.0f) ? 1.0f : 0.0f;
        mem1 -= spk;
        spk1[((size_t)t * BATCH + b) * NH + j] = spk;
    }
}

// ---------------------------------------------------------------------------
// layer2k: cur2[t,b,o] with round-1's EXACT reduction tree:
// per warp-slice w: p = spk1 * W2, 5-step xor-butterfly (identical lane
// data), take LANE 0's value (what round-1 deposits), accumulate in
// ascending-w order starting from bias2. One warp per (t,b) pair.
// ---------------------------------------------------------------------------
__global__ __launch_bounds__(256) void layer2k(const float* __restrict__ spk1,
                                               const float* __restrict__ W2,
                                               const float* __restrict__ b2,
                                               float* __restrict__ cur2) {
    const int w8  = threadIdx.x >> 5;     // warp in block
    const int lid = threadIdx.x & 31;
    const int tb  = blockIdx.x * 8 + w8;  // 0..6399  (= t*BATCH + b)

    float acc[NO];
#pragma unroll
    for (int o = 0; o < NO; o++) acc[o] = b2[o];

    const float* srow = spk1 + (size_t)tb * NH;

#pragma unroll
    for (int w = 0; w < 8; w++) {
        const float s = srow[w * 32 + lid];
        float p[NO];
#pragma unroll
        for (int o = 0; o < NO; o++) p[o] = s * W2[o * NH + w * 32 + lid];
#pragma unroll
        for (int o = 0; o < NO; o++) {
#pragma unroll
            for (int off = 16; off > 0; off >>= 1)
                p[o] += __shfl_xor_sync(0xFFFFFFFFu, p[o], off);
        }
        // round-1 stores lane 0's butterfly result; replicate exactly
#pragma unroll
        for (int o = 0; o < NO; o++) {
            const float q0 = __shfl_sync(0xFFFFFFFFu, p[o], 0);
            acc[o] += q0;
        }
    }

    if (lid < NO)
        cur2[(size_t)tb * NO + lid] = acc[lid];
}

// ---------------------------------------------------------------------------
// scan2: 1408 independent layer-2 membrane chains; identical expressions.
// ---------------------------------------------------------------------------
__global__ __launch_bounds__(256) void scan2(const float* __restrict__ cur2,
                                             float* __restrict__ out) {
    const int gid = blockIdx.x * 256 + threadIdx.x;
    if (gid >= BATCH * NO) return;
    float mem2 = 0.0f;
#pragma unroll 5
    for (int t = 0; t < T_STEPS; t++) {
        const float c2 = cur2[(size_t)t * BATCH * NO + gid];
        mem2 = 0.9f * mem2 + c2;
        const float spk = (mem2 - 1.0f > 0.0f) ? 1.0f : 0.0f;
        mem2 -= spk;
        out[(size_t)t * BATCH * NO + gid] = spk;
    }
}

// ---------------------------------------------------------------------------
extern "C" void kernel_launch(void* const* d_in, const int* in_sizes, int n_in,
                              void* d_out, int out_size)
{
    const float* x  = (const float*)d_in[0];   // [50,128,128,128]
    const float* W1 = (const float*)d_in[1];   // [256,16384]
    const float* b1 = (const float*)d_in[2];   // [256]
    const float* W2 = (const float*)d_in[3];   // [11,256]
    const float* b2 = (const float*)d_in[4];   // [11]
    float* out = (float*)d_out;                // [50,128,11]

    float *cur1, *spk1, *cur2;
    cudaGetSymbolAddress((void**)&cur1, g_cur1);
    cudaGetSymbolAddress((void**)&spk1, g_spk1);
    cudaGetSymbolAddress((void**)&cur2, g_cur2);

    dim3 ggrid(NH / BN, M_TOT / BM);   // (4, 100)
    gemm_x_w1<<<ggrid, 128>>>(x, W1, b1, cur1);

    scan1<<<BATCH, NH>>>(cur1, spk1);
    layer2k<<<M_TOT / 8, 256>>>(spk1, W2, b2, cur2);
    scan2<<<(BATCH * NO + 255) / 256, 256>>>(cur2, out);
}